// round 15
// baseline (speedup 1.0000x reference)
#include <cuda_runtime.h>
#include <cuda_bf16.h>
#include <cuda_fp8.h>
#include <stdint.h>
#include <math.h>

#define NROWS 8192
#define HALF_N 4096
#define DDIM 256
#define NCTA 296

// Scratch (allocation-free rule: __device__ globals)
__device__ uint8_t g_reps[NROWS * DDIM];        // e4m3, normalized * sqrt(2*log2 e)
__device__ float g_den[NROWS];                  // denominator sums (atomic accum)
__device__ float g_pos[NROWS];                  // positive logit (natural log domain)
__device__ float g_rpart[32];
__device__ int g_sem;                           // zero-init; reset each launch

static __device__ __forceinline__ float ex2f(float x) {
    float y;
    asm("ex2.approx.f32 %0, %1;" : "=f"(y) : "f"(x));
    return y;
}

static __device__ __forceinline__ void ldsm4(uint32_t& r0, uint32_t& r1,
                                             uint32_t& r2, uint32_t& r3, uint32_t addr) {
    asm volatile("ldmatrix.sync.aligned.m8n8.x4.shared.b16 {%0,%1,%2,%3}, [%4];"
                 : "=r"(r0), "=r"(r1), "=r"(r2), "=r"(r3) : "r"(addr));
}

// fp8 e4m3 MMA, k32 per instruction, fp32 accum (accum layout == m16n8k16).
static __device__ __forceinline__ void mma_fp8(float c[4], const uint32_t a[4],
                                               const uint32_t b[2]) {
    asm volatile(
        "mma.sync.aligned.m16n8k32.row.col.f32.e4m3.e4m3.f32 "
        "{%0,%1,%2,%3}, {%4,%5,%6,%7}, {%8,%9}, {%0,%1,%2,%3};"
        : "+f"(c[0]), "+f"(c[1]), "+f"(c[2]), "+f"(c[3])
        : "r"(a[0]), "r"(a[1]), "r"(a[2]), "r"(a[3]), "r"(b[0]), "r"(b[1]));
}

static __device__ __forceinline__ void cpasync16(uint32_t dst, const void* src) {
    asm volatile("cp.async.cg.shared.global [%0], [%1], 16;" :: "r"(dst), "l"(src));
}
#define CP_COMMIT() asm volatile("cp.async.commit_group;")
#define CP_WAIT1()  asm volatile("cp.async.wait_group 1;")
#define CP_WAIT0()  asm volatile("cp.async.wait_group 0;")

static __device__ __forceinline__ uint16_t cvt_e4m3x2(float hi, float lo) {
    uint16_t r;
    asm("cvt.rn.satfinite.e4m3x2.f32 %0, %1, %2;" : "=h"(r) : "f"(hi), "f"(lo));
    return r;
}

// Advance (rb, cb) one tile along the upper triangle (rb-major, cb contiguous).
#define ADV(r_, c_) do { if ((c_) >= 63) { if ((r_) < 63) { (r_)++; (c_) = (r_); } } \
                         else (c_)++; } while (0)

// smem per CTA: A 32KB @0 ; B full-tile bufs 32KB @32768, @65536. Total 96KB.
#define SM_B0 32768u
#define SM_B1 65536u
#define SM_TOTAL 98304u

// Swizzled 16B-chunk offset within a 256B row (16 chunks; keep bit3, XOR low 3).
static __device__ __forceinline__ uint32_t swz(int chunk, int r) {
    return (uint32_t)(((chunk & 8) | ((chunk & 7) ^ (r & 7))) << 4);
}

// Fill one full fp8 tile (128 rows x 256B = 32KB) with 128 threads.
static __device__ __forceinline__ void fill_tile(uint32_t dst, const uint4* src, int tid) {
#pragma unroll
    for (int it = 0; it < 16; it++) {
        int idx = it * 128 + tid;
        int r = idx >> 4, c = idx & 15;
        cpasync16(dst + (uint32_t)(r * 256) + swz(c, r), src + idx);
    }
}

// ---------------------------------------------------------------------------
// Kernel 1: L2-normalize rows; e4m3 scaled by sqrt(2*log2 e) (product of two
// rows carries 2*log2 e -> base-2 logits). Zeroes g_den.
// ---------------------------------------------------------------------------
__global__ void k_norm(const float* __restrict__ ei, const float* __restrict__ ej) {
    const float SQ = 1.69864362f;  // sqrt(2 * log2(e))
    int warp = threadIdx.x >> 5;
    int lane = threadIdx.x & 31;
    int row = blockIdx.x * 16 + warp * 2;

    const float* s0 = (row < HALF_N) ? (ei + (size_t)row * DDIM)
                                     : (ej + (size_t)(row - HALF_N) * DDIM);
    const float* s1 = s0 + DDIM;
    float4 a0 = ((const float4*)s0)[lane * 2];
    float4 a1 = ((const float4*)s0)[lane * 2 + 1];
    float4 b0 = ((const float4*)s1)[lane * 2];
    float4 b1 = ((const float4*)s1)[lane * 2 + 1];

    float sa = a0.x * a0.x + a0.y * a0.y + a0.z * a0.z + a0.w * a0.w
             + a1.x * a1.x + a1.y * a1.y + a1.z * a1.z + a1.w * a1.w;
    float sb = b0.x * b0.x + b0.y * b0.y + b0.z * b0.z + b0.w * b0.w
             + b1.x * b1.x + b1.y * b1.y + b1.z * b1.z + b1.w * b1.w;
#pragma unroll
    for (int o = 16; o > 0; o >>= 1) {
        sa += __shfl_xor_sync(0xFFFFFFFFu, sa, o);
        sb += __shfl_xor_sync(0xFFFFFFFFu, sb, o);
    }
    float fa = SQ / fmaxf(sqrtf(sa), 1e-12f);
    float fb = SQ / fmaxf(sqrtf(sb), 1e-12f);

    uint32_t pa0 = (uint32_t)cvt_e4m3x2(a0.y * fa, a0.x * fa)
                 | ((uint32_t)cvt_e4m3x2(a0.w * fa, a0.z * fa) << 16);
    uint32_t pa1 = (uint32_t)cvt_e4m3x2(a1.y * fa, a1.x * fa)
                 | ((uint32_t)cvt_e4m3x2(a1.w * fa, a1.z * fa) << 16);
    uint32_t pb0 = (uint32_t)cvt_e4m3x2(b0.y * fb, b0.x * fb)
                 | ((uint32_t)cvt_e4m3x2(b0.w * fb, b0.z * fb) << 16);
    uint32_t pb1 = (uint32_t)cvt_e4m3x2(b1.y * fb, b1.x * fb)
                 | ((uint32_t)cvt_e4m3x2(b1.w * fb, b1.z * fb) << 16);

    *(uint2*)(g_reps + (size_t)row * DDIM + lane * 8) = make_uint2(pa0, pa1);
    *(uint2*)(g_reps + (size_t)(row + 1) * DDIM + lane * 8) = make_uint2(pb0, pb1);
    if (lane == 0) { g_den[row] = 0.f; g_den[row + 1] = 0.f; }
}

// ---------------------------------------------------------------------------
// Kernel 2: symmetric fused FP8 GEMM + exp + row/col sums (upper triangle).
// 296 CTAs x 128 threads, 2 CTAs/SM. 4 warps of 64x64; fp8 operands halve
// LDSM bytes/tile vs bf16 (128KB) and full B tiles (32KB) double-buffer in
// smem with only 2 syncs per tile. A resident per stripe.
// ---------------------------------------------------------------------------
__global__ void __launch_bounds__(128, 2) k_main() {
    extern __shared__ unsigned char smem[];
    const float LN2 = 0.6931471805599453f;

    int tid = threadIdx.x;
    int lane = tid & 31;
    int warp = tid >> 5;
    int wm = warp >> 1;   // 0..1: 64-row half
    int wn = warp & 1;    // 0..1: 64-col half

    uint32_t sb = (uint32_t)__cvta_generic_to_shared(smem);
    const uint4* reps16 = (const uint4*)g_reps;   // 16B chunks; 16 per row

    // ---- schedule: 2080 = 296*7 + 8 ; extras on bids 0..7 (distinct SMs)
    int bId = blockIdx.x;
    int cnt = 7 + (bId < 8 ? 1 : 0);
    int i0 = bId * 7 + (bId < 8 ? bId : 8);

    int rb = 0, rem = i0;
    while (rem >= 64 - rb) { rem -= 64 - rb; rb++; }
    int cb = rb + rem;
    int rb1 = rb, cb1 = cb; ADV(rb1, cb1);
    int rbp = rb1, cbp = cb1; ADV(rbp, cbp);

    // Prologue: A(rb) + B tile 0, then B tile 1.
    fill_tile(sb, reps16 + (size_t)(rb * 128) * 16, tid);
    fill_tile(sb + SM_B0, reps16 + (size_t)(cb * 128) * 16, tid);
    CP_COMMIT();
    if (cnt > 1) fill_tile(sb + SM_B1, reps16 + (size_t)(cb1 * 128) * 16, tid);
    CP_COMMIT();
    CP_WAIT1();
    __syncthreads();

    int aRow0 = wm * 64 + (lane & 15);
    int aCo = lane >> 4;
    int bRowBase = wn * 64 + (lane & 7) + ((lane & 16) >> 1);
    int bCo = (lane >> 3) & 1;

    float s[8];
#pragma unroll
    for (int i = 0; i < 8; i++) s[i] = 0.f;
    int b = 0;

#pragma unroll 1
    for (int k = 0; ; k++) {
        uint32_t Bs = sb + (b ? SM_B1 : SM_B0);

        float acc[4][8][4];
#pragma unroll
        for (int mt = 0; mt < 4; mt++)
#pragma unroll
            for (int nt = 0; nt < 8; nt++)
#pragma unroll
                for (int e = 0; e < 4; e++) acc[mt][nt][e] = 0.f;

#pragma unroll
        for (int ks = 0; ks < 8; ks++) {   // k32 per step, K=256
            uint32_t a[4][4];
#pragma unroll
            for (int mt = 0; mt < 4; mt++) {
                int r = aRow0 + mt * 16;
                uint32_t addr = sb + r * 256 + swz(ks * 2 + aCo, r);
                ldsm4(a[mt][0], a[mt][1], a[mt][2], a[mt][3], addr);
            }
            uint32_t bf[8][2];
#pragma unroll
            for (int nb = 0; nb < 4; nb++) {
                int r = bRowBase + nb * 16;
                uint32_t addr = Bs + r * 256 + swz(ks * 2 + bCo, r);
                uint32_t r0, r1, r2, r3;
                ldsm4(r0, r1, r2, r3, addr);
                bf[nb * 2][0] = r0;     bf[nb * 2][1] = r1;
                bf[nb * 2 + 1][0] = r2; bf[nb * 2 + 1][1] = r3;
            }
#pragma unroll
            for (int mt = 0; mt < 4; mt++)
#pragma unroll
                for (int nt = 0; nt < 8; nt++)
                    mma_fp8(acc[mt][nt], a[mt], bf[nt]);
        }

        // ---- Epilogue: exps, row sums (registers), col sums (shfl+atomics).
        bool diagblk = (rb == cb);
        bool posblk = (cb == rb + 32);
        bool special = diagblk || posblk;
        float cs[16];
#pragma unroll
        for (int q = 0; q < 16; q++) cs[q] = 0.f;

#pragma unroll
        for (int mt = 0; mt < 4; mt++) {
            int lrA = wm * 64 + mt * 16 + (lane >> 2);
            int lrB = lrA + 8;
#pragma unroll
            for (int nt = 0; nt < 8; nt++) {
                float vx = acc[mt][nt][0], vy = acc[mt][nt][1];
                float vz = acc[mt][nt][2], vw = acc[mt][nt][3];
                int lc = wn * 64 + nt * 8 + (lane & 3) * 2;
                float e0 = ex2f(vx), e1 = ex2f(vy), e2 = ex2f(vz), e3 = ex2f(vw);
                if (special) {
                    if (lc == lrA) {
                        if (diagblk) e0 = 0.f;
                        else { int gr = rb * 128 + lrA; float pv = vx * LN2;
                               g_pos[gr] = pv; g_pos[gr + 4096] = pv; }
                    }
                    if (lc + 1 == lrA) {
                        if (diagblk) e1 = 0.f;
                        else { int gr = rb * 128 + lrA; float pv = vy * LN2;
                               g_pos[gr] = pv; g_pos[gr + 4096] = pv; }
                    }
                    if (lc == lrB) {
                        if (diagblk) e2 = 0.f;
                        else { int gr = rb * 128 + lrB; float pv = vz * LN2;
                               g_pos[gr] = pv; g_pos[gr + 4096] = pv; }
                    }
                    if (lc + 1 == lrB) {
                        if (diagblk) e3 = 0.f;
                        else { int gr = rb * 128 + lrB; float pv = vw * LN2;
                               g_pos[gr] = pv; g_pos[gr + 4096] = pv; }
                    }
                }
                s[mt * 2 + 0] += e0 + e1;
                s[mt * 2 + 1] += e2 + e3;
                cs[nt * 2 + 0] += e0 + e2;
                cs[nt * 2 + 1] += e1 + e3;
            }
        }

        if (!diagblk) {
#pragma unroll
            for (int q = 0; q < 16; q++) {
                cs[q] += __shfl_xor_sync(0xFFFFFFFFu, cs[q], 4);
                cs[q] += __shfl_xor_sync(0xFFFFFFFFu, cs[q], 8);
                cs[q] += __shfl_xor_sync(0xFFFFFFFFu, cs[q], 16);
            }
            if (lane < 4) {
                int cbase = cb * 128 + wn * 64 + lane * 2;
#pragma unroll
                for (int nt = 0; nt < 8; nt++) {
                    atomicAdd(&g_den[cbase + nt * 8 + 0], cs[nt * 2 + 0]);
                    atomicAdd(&g_den[cbase + nt * 8 + 1], cs[nt * 2 + 1]);
                }
            }
        }

        __syncthreads();  // all warps done reading B[b] (and A before reload)

        // Prefetch tile k+2 into the just-freed buffer.
        if (k + 2 < cnt)
            fill_tile(sb + (b ? SM_B1 : SM_B0),
                      reps16 + (size_t)(cbp * 128) * 16, tid);
        CP_COMMIT();      // possibly empty; keeps WAIT1 accounting uniform

        if (k + 1 >= cnt) break;
        ADV(rbp, cbp);

        if (rb1 != rb) {
            // Stripe change: flush row sums, reload A, drain everything.
#pragma unroll
            for (int i2 = 0; i2 < 8; i2++) {
                s[i2] += __shfl_xor_sync(0xFFFFFFFFu, s[i2], 1);
                s[i2] += __shfl_xor_sync(0xFFFFFFFFu, s[i2], 2);
            }
            if ((lane & 3) == 0) {
#pragma unroll
                for (int mt = 0; mt < 4; mt++) {
                    int r = rb * 128 + wm * 64 + mt * 16 + (lane >> 2);
                    atomicAdd(&g_den[r], s[mt * 2]);
                    atomicAdd(&g_den[r + 8], s[mt * 2 + 1]);
                }
            }
#pragma unroll
            for (int i2 = 0; i2 < 8; i2++) s[i2] = 0.f;
            fill_tile(sb, reps16 + (size_t)(rb1 * 128) * 16, tid);
            CP_COMMIT();
            CP_WAIT0();
        } else {
            CP_WAIT1();
        }
        __syncthreads();

        rb = rb1; cb = cb1;
        ADV(rb1, cb1);
        b ^= 1;
    }

    // Final row-sum flush.
#pragma unroll
    for (int i2 = 0; i2 < 8; i2++) {
        s[i2] += __shfl_xor_sync(0xFFFFFFFFu, s[i2], 1);
        s[i2] += __shfl_xor_sync(0xFFFFFFFFu, s[i2], 2);
    }
    if ((lane & 3) == 0) {
#pragma unroll
        for (int mt = 0; mt < 4; mt++) {
            int r = rb * 128 + wm * 64 + mt * 16 + (lane >> 2);
            atomicAdd(&g_den[r], s[mt * 2]);
            atomicAdd(&g_den[r + 8], s[mt * 2 + 1]);
        }
    }
}

// ---------------------------------------------------------------------------
// Kernel 3: final reduction -> scalar loss (deterministic fixed-order finish).
// ---------------------------------------------------------------------------
__global__ void k_reduce(float* __restrict__ out) {
    __shared__ float red[256];
    __shared__ int isLast;
    int tid = threadIdx.x;
    int r = blockIdx.x * 256 + tid;
    red[tid] = logf(g_den[r]) - g_pos[r];
    __syncthreads();
#pragma unroll
    for (int o = 128; o > 0; o >>= 1) {
        if (tid < o) red[tid] += red[tid + o];
        __syncthreads();
    }
    if (tid == 0) {
        g_rpart[blockIdx.x] = red[0];
        __threadfence();
        int old = atomicAdd(&g_sem, 1);
        isLast = (old == 31);
    }
    __syncthreads();
    if (tid == 0 && isLast) {
        __threadfence();
        volatile float* rp = g_rpart;
        float a = 0.f;
        for (int i = 0; i < 32; i++) a += rp[i];
        out[0] = a * (1.0f / 8192.0f);
        g_sem = 0;
    }
}

extern "C" void kernel_launch(void* const* d_in, const int* in_sizes, int n_in,
                              void* d_out, int out_size) {
    const float* ei = (const float*)d_in[0];
    const float* ej = (const float*)d_in[1];
    (void)in_sizes; (void)n_in; (void)out_size;

    cudaFuncSetAttribute(k_main, cudaFuncAttributeMaxDynamicSharedMemorySize, SM_TOTAL);

    k_norm<<<512, 256>>>(ei, ej);
    k_main<<<NCTA, 128, SM_TOTAL>>>();
    k_reduce<<<32, 256>>>((float*)d_out);
}